// round 3
// baseline (speedup 1.0000x reference)
#include <cuda_runtime.h>

#define N_NODES  100000
#define IN_DIM   256
#define OUT_DIM  128
#define FEAT_NNZ 1000000
#define ADJ_NNZ  1600000

#define SCAN_THREADS 1024
#define SCAN_CHUNK   98          // 1024 * 98 = 100352 >= 100000

// ---------------------------------------------------------------------------
// Scratch (__device__ globals; referenced ONLY from device code)
// ---------------------------------------------------------------------------
__device__ float  g_xw[(size_t)N_NODES * OUT_DIM];        // 51.2 MB

__device__ int    g_feat_cnt [N_NODES];
__device__ int    g_feat_ptr [N_NODES + 1];
__device__ int    g_feat_next[N_NODES];
__device__ float2 g_feat_csr [FEAT_NNZ];                  // {val, col bits}

__device__ int    g_adj_cnt [N_NODES];
__device__ int    g_adj_ptr [N_NODES + 1];
__device__ int    g_adj_next[N_NODES];
__device__ float2 g_adj_csr [ADJ_NNZ];

// ---------------------------------------------------------------------------
// 1. Zero the two histogram arrays (800 KB).
// ---------------------------------------------------------------------------
__global__ void zero_counters_kernel() {
    int i = blockIdx.x * blockDim.x + threadIdx.x;
    if (i < N_NODES) {
        g_feat_cnt[i] = 0;
        g_adj_cnt[i]  = 0;
    }
}

// ---------------------------------------------------------------------------
// 2. Row histogram (one thread per nnz). which=0 -> feat, which=1 -> adj.
// ---------------------------------------------------------------------------
__global__ void hist_kernel(const int* __restrict__ rows, int nnz, int which) {
    int* __restrict__ cnt = which ? g_adj_cnt : g_feat_cnt;
    int i = blockIdx.x * blockDim.x + threadIdx.x;
    if (i < nnz) atomicAdd(&cnt[rows[i]], 1);
}

// ---------------------------------------------------------------------------
// 3. Exclusive prefix sum over N_NODES counts, one block of 1024 threads.
//    Writes ptr[] and a working copy next[] for the scatter pass.
// ---------------------------------------------------------------------------
__global__ void scan_kernel(int which) {
    const int* __restrict__ cnt = which ? g_adj_cnt : g_feat_cnt;
    int* __restrict__ ptr  = which ? g_adj_ptr  : g_feat_ptr;
    int* __restrict__ next = which ? g_adj_next : g_feat_next;

    __shared__ int ssum[SCAN_THREADS];
    int t = threadIdx.x;
    int base = t * SCAN_CHUNK;

    int local = 0;
    #pragma unroll 2
    for (int i = 0; i < SCAN_CHUNK; i++) {
        int idx = base + i;
        if (idx < N_NODES) local += cnt[idx];
    }
    ssum[t] = local;
    __syncthreads();

    // inclusive Hillis-Steele over the 1024 chunk sums
    for (int off = 1; off < SCAN_THREADS; off <<= 1) {
        int v = (t >= off) ? ssum[t - off] : 0;
        __syncthreads();
        ssum[t] += v;
        __syncthreads();
    }

    int run = (t == 0) ? 0 : ssum[t - 1];   // exclusive prefix of this chunk
    #pragma unroll 2
    for (int i = 0; i < SCAN_CHUNK; i++) {
        int idx = base + i;
        if (idx < N_NODES) {
            ptr[idx]  = run;
            next[idx] = run;
            run += cnt[idx];
        }
    }
    if (t == SCAN_THREADS - 1) ptr[N_NODES] = run;
}

// ---------------------------------------------------------------------------
// 4. Scatter COO entries into CSR slots (val+col packed into one 8B store).
// ---------------------------------------------------------------------------
__global__ void scatter_kernel(const float* __restrict__ vals,
                               const int*   __restrict__ rows,
                               const int*   __restrict__ cols,
                               int nnz, int which) {
    int* __restrict__ next   = which ? g_adj_next : g_feat_next;
    float2* __restrict__ csr = which ? g_adj_csr  : g_feat_csr;

    int i = blockIdx.x * blockDim.x + threadIdx.x;
    if (i >= nnz) return;
    int pos = atomicAdd(&next[rows[i]], 1);
    csr[pos] = make_float2(vals[i], __int_as_float(cols[i]));
}

// ---------------------------------------------------------------------------
// 5. SpMM1 (CSR gather): XW[row,:] = sum_e val_e * W[col_e,:]
//    Warp per row; lane owns a float4 of OUT columns. W (128 KB) L1-resident.
// ---------------------------------------------------------------------------
__global__ void spmm1_csr_kernel(const float4* __restrict__ W4) {
    int row  = blockIdx.x * (blockDim.x >> 5) + (threadIdx.x >> 5);
    if (row >= N_NODES) return;
    int lane = threadIdx.x & 31;

    int s = g_feat_ptr[row];
    int e = g_feat_ptr[row + 1];

    float4 acc = make_float4(0.f, 0.f, 0.f, 0.f);
    for (int j = s; j < e; j++) {
        float2 vc = __ldg(&g_feat_csr[j]);          // uniform across warp
        float v = vc.x;
        int   c = __float_as_int(vc.y);
        float4 w = __ldg(&W4[(size_t)c * 32 + lane]);
        acc.x += v * w.x;
        acc.y += v * w.y;
        acc.z += v * w.z;
        acc.w += v * w.w;
    }
    ((float4*)g_xw)[(size_t)row * 32 + lane] = acc;
}

// ---------------------------------------------------------------------------
// 6. SpMM2 (CSR gather) + fused bias + ReLU. XW (51.2 MB) L2-resident.
// ---------------------------------------------------------------------------
__global__ void spmm2_csr_kernel(float4* __restrict__ out4,
                                 const float4* __restrict__ bias4) {
    int row  = blockIdx.x * (blockDim.x >> 5) + (threadIdx.x >> 5);
    if (row >= N_NODES) return;
    int lane = threadIdx.x & 31;

    int s = g_adj_ptr[row];
    int e = g_adj_ptr[row + 1];

    float4 acc = make_float4(0.f, 0.f, 0.f, 0.f);
    const float4* xw4 = (const float4*)g_xw;
    for (int j = s; j < e; j++) {
        float2 vc = __ldg(&g_adj_csr[j]);           // uniform across warp
        float v = vc.x;
        int   c = __float_as_int(vc.y);
        float4 x = __ldg(&xw4[(size_t)c * 32 + lane]);
        acc.x += v * x.x;
        acc.y += v * x.y;
        acc.z += v * x.z;
        acc.w += v * x.w;
    }

    float4 b = __ldg(&bias4[lane]);
    acc.x = fmaxf(acc.x + b.x, 0.f);
    acc.y = fmaxf(acc.y + b.y, 0.f);
    acc.z = fmaxf(acc.z + b.z, 0.f);
    acc.w = fmaxf(acc.w + b.w, 0.f);
    out4[(size_t)row * 32 + lane] = acc;
}

// ---------------------------------------------------------------------------
extern "C" void kernel_launch(void* const* d_in, const int* in_sizes, int n_in,
                              void* d_out, int out_size) {
    const float* feat_vals = (const float*)d_in[0];
    const int*   feat_rows = (const int*)  d_in[1];
    const int*   feat_cols = (const int*)  d_in[2];
    const float* adj_vals  = (const float*)d_in[3];
    const int*   adj_rows  = (const int*)  d_in[4];
    const int*   adj_cols  = (const int*)  d_in[5];
    const float* weights   = (const float*)d_in[6];
    const float* bias_vec  = (const float*)d_in[7];
    float4* out4 = (float4*)d_out;

    const int T = 256;

    zero_counters_kernel<<<(N_NODES + T - 1) / T, T>>>();

    hist_kernel<<<(FEAT_NNZ + T - 1) / T, T>>>(feat_rows, FEAT_NNZ, 0);
    hist_kernel<<<(ADJ_NNZ  + T - 1) / T, T>>>(adj_rows,  ADJ_NNZ,  1);

    scan_kernel<<<1, SCAN_THREADS>>>(0);
    scan_kernel<<<1, SCAN_THREADS>>>(1);

    scatter_kernel<<<(FEAT_NNZ + T - 1) / T, T>>>(feat_vals, feat_rows, feat_cols,
                                                  FEAT_NNZ, 0);
    scatter_kernel<<<(ADJ_NNZ + T - 1) / T, T>>>(adj_vals, adj_rows, adj_cols,
                                                 ADJ_NNZ, 1);

    const int rows_grid = (N_NODES + 7) / 8;   // 8 warps/block, warp per row
    spmm1_csr_kernel<<<rows_grid, T>>>((const float4*)weights);
    spmm2_csr_kernel<<<rows_grid, T>>>(out4, (const float4*)bias_vec);
}

// round 4
// speedup vs baseline: 2.7539x; 2.7539x over previous
#include <cuda_runtime.h>

#define N_NODES  100000
#define IN_DIM   256
#define OUT_DIM  128
#define FEAT_NNZ 1000000
#define ADJ_NNZ  1600000

#define TILE      1024
#define NBLK      ((N_NODES + TILE - 1) / TILE)   // 98

// ---------------------------------------------------------------------------
// Scratch (__device__ globals; referenced ONLY from device code)
// ---------------------------------------------------------------------------
__device__ float  g_xw[(size_t)N_NODES * OUT_DIM];        // 51.2 MB

__device__ int    g_feat_cnt [N_NODES];
__device__ int    g_feat_ptr [N_NODES + 1];
__device__ int    g_feat_next[N_NODES];
__device__ float2 g_feat_csr [FEAT_NNZ];                  // {val, col bits}
__device__ int    g_feat_bsum[NBLK];
__device__ int    g_feat_boff[NBLK];

__device__ int    g_adj_cnt [N_NODES];
__device__ int    g_adj_ptr [N_NODES + 1];
__device__ int    g_adj_next[N_NODES];
__device__ float2 g_adj_csr [ADJ_NNZ];
__device__ int    g_adj_bsum[NBLK];
__device__ int    g_adj_boff[NBLK];

// ---------------------------------------------------------------------------
// 1. Zero the two histogram arrays (800 KB).
// ---------------------------------------------------------------------------
__global__ void zero_counters_kernel() {
    int i = blockIdx.x * blockDim.x + threadIdx.x;
    if (i < N_NODES) {
        g_feat_cnt[i] = 0;
        g_adj_cnt[i]  = 0;
    }
}

// ---------------------------------------------------------------------------
// 2. Row histogram (one thread per nnz). which=0 -> feat, which=1 -> adj.
// ---------------------------------------------------------------------------
__global__ void hist_kernel(const int* __restrict__ rows, int nnz, int which) {
    int* __restrict__ cnt = which ? g_adj_cnt : g_feat_cnt;
    int i = blockIdx.x * blockDim.x + threadIdx.x;
    if (i < nnz) atomicAdd(&cnt[rows[i]], 1);
}

// ---------------------------------------------------------------------------
// 3a. Scan phase 1: per-tile sums (98 blocks x 1024 threads).
// ---------------------------------------------------------------------------
__global__ void scan_p1_kernel(int which) {
    const int* __restrict__ cnt = which ? g_adj_cnt  : g_feat_cnt;
    int* __restrict__ bsum      = which ? g_adj_bsum : g_feat_bsum;

    __shared__ int s[TILE];
    int t   = threadIdx.x;
    int idx = blockIdx.x * TILE + t;
    s[t] = (idx < N_NODES) ? cnt[idx] : 0;
    __syncthreads();
    for (int off = TILE >> 1; off > 0; off >>= 1) {
        if (t < off) s[t] += s[t + off];
        __syncthreads();
    }
    if (t == 0) bsum[blockIdx.x] = s[0];
}

// ---------------------------------------------------------------------------
// 3b. Scan phase 2: exclusive scan of the 98 tile sums (one tiny block).
// ---------------------------------------------------------------------------
__global__ void scan_p2_kernel(int which) {
    const int* __restrict__ bsum = which ? g_adj_bsum : g_feat_bsum;
    int* __restrict__ boff       = which ? g_adj_boff : g_feat_boff;
    int* __restrict__ ptr        = which ? g_adj_ptr  : g_feat_ptr;

    __shared__ int s[128];
    int t = threadIdx.x;
    int v = (t < NBLK) ? bsum[t] : 0;
    s[t] = v;
    __syncthreads();
    for (int off = 1; off < 128; off <<= 1) {
        int u = (t >= off) ? s[t - off] : 0;
        __syncthreads();
        s[t] += u;
        __syncthreads();
    }
    if (t < NBLK) boff[t] = s[t] - v;          // exclusive
    if (t == NBLK - 1) ptr[N_NODES] = s[t];    // total nnz
}

// ---------------------------------------------------------------------------
// 3c. Scan phase 3: smem scan within each tile + tile offset; writes ptr+next.
// ---------------------------------------------------------------------------
__global__ void scan_p3_kernel(int which) {
    const int* __restrict__ cnt  = which ? g_adj_cnt  : g_feat_cnt;
    const int* __restrict__ boff = which ? g_adj_boff : g_feat_boff;
    int* __restrict__ ptr        = which ? g_adj_ptr  : g_feat_ptr;
    int* __restrict__ next       = which ? g_adj_next : g_feat_next;

    __shared__ int s[TILE];
    int t   = threadIdx.x;
    int idx = blockIdx.x * TILE + t;
    int v   = (idx < N_NODES) ? cnt[idx] : 0;
    s[t] = v;
    __syncthreads();
    // inclusive Hillis-Steele over the tile
    for (int off = 1; off < TILE; off <<= 1) {
        int u = (t >= off) ? s[t - off] : 0;
        __syncthreads();
        s[t] += u;
        __syncthreads();
    }
    if (idx < N_NODES) {
        int excl = boff[blockIdx.x] + s[t] - v;
        ptr[idx]  = excl;
        next[idx] = excl;
    }
}

// ---------------------------------------------------------------------------
// 4. Scatter COO entries into CSR slots (val+col packed into one 8B store).
// ---------------------------------------------------------------------------
__global__ void scatter_kernel(const float* __restrict__ vals,
                               const int*   __restrict__ rows,
                               const int*   __restrict__ cols,
                               int nnz, int which) {
    int* __restrict__ next   = which ? g_adj_next : g_feat_next;
    float2* __restrict__ csr = which ? g_adj_csr  : g_feat_csr;

    int i = blockIdx.x * blockDim.x + threadIdx.x;
    if (i >= nnz) return;
    int pos = atomicAdd(&next[rows[i]], 1);
    csr[pos] = make_float2(vals[i], __int_as_float(cols[i]));
}

// ---------------------------------------------------------------------------
// 5. SpMM1 (CSR gather): XW[row,:] = sum_e val_e * W[col_e,:]
//    Warp per row; lane owns a float4 of OUT columns. W (128 KB) L1-resident.
// ---------------------------------------------------------------------------
__global__ void spmm1_csr_kernel(const float4* __restrict__ W4) {
    int row  = blockIdx.x * (blockDim.x >> 5) + (threadIdx.x >> 5);
    if (row >= N_NODES) return;
    int lane = threadIdx.x & 31;

    int s = g_feat_ptr[row];
    int e = g_feat_ptr[row + 1];

    float4 acc = make_float4(0.f, 0.f, 0.f, 0.f);
    for (int j = s; j < e; j++) {
        float2 vc = __ldg(&g_feat_csr[j]);          // uniform across warp
        float v = vc.x;
        int   c = __float_as_int(vc.y);
        float4 w = __ldg(&W4[(size_t)c * 32 + lane]);
        acc.x += v * w.x;
        acc.y += v * w.y;
        acc.z += v * w.z;
        acc.w += v * w.w;
    }
    ((float4*)g_xw)[(size_t)row * 32 + lane] = acc;
}

// ---------------------------------------------------------------------------
// 6. SpMM2 (CSR gather) + fused bias + ReLU. XW (51.2 MB) L2-resident.
// ---------------------------------------------------------------------------
__global__ void spmm2_csr_kernel(float4* __restrict__ out4,
                                 const float4* __restrict__ bias4) {
    int row  = blockIdx.x * (blockDim.x >> 5) + (threadIdx.x >> 5);
    if (row >= N_NODES) return;
    int lane = threadIdx.x & 31;

    int s = g_adj_ptr[row];
    int e = g_adj_ptr[row + 1];

    float4 acc = make_float4(0.f, 0.f, 0.f, 0.f);
    const float4* xw4 = (const float4*)g_xw;
    for (int j = s; j < e; j++) {
        float2 vc = __ldg(&g_adj_csr[j]);           // uniform across warp
        float v = vc.x;
        int   c = __float_as_int(vc.y);
        float4 x = __ldg(&xw4[(size_t)c * 32 + lane]);
        acc.x += v * x.x;
        acc.y += v * x.y;
        acc.z += v * x.z;
        acc.w += v * x.w;
    }

    float4 b = __ldg(&bias4[lane]);
    acc.x = fmaxf(acc.x + b.x, 0.f);
    acc.y = fmaxf(acc.y + b.y, 0.f);
    acc.z = fmaxf(acc.z + b.z, 0.f);
    acc.w = fmaxf(acc.w + b.w, 0.f);
    out4[(size_t)row * 32 + lane] = acc;
}

// ---------------------------------------------------------------------------
extern "C" void kernel_launch(void* const* d_in, const int* in_sizes, int n_in,
                              void* d_out, int out_size) {
    const float* feat_vals = (const float*)d_in[0];
    const int*   feat_rows = (const int*)  d_in[1];
    const int*   feat_cols = (const int*)  d_in[2];
    const float* adj_vals  = (const float*)d_in[3];
    const int*   adj_rows  = (const int*)  d_in[4];
    const int*   adj_cols  = (const int*)  d_in[5];
    const float* weights   = (const float*)d_in[6];
    const float* bias_vec  = (const float*)d_in[7];
    float4* out4 = (float4*)d_out;

    const int T = 256;

    zero_counters_kernel<<<(N_NODES + T - 1) / T, T>>>();

    hist_kernel<<<(FEAT_NNZ + T - 1) / T, T>>>(feat_rows, FEAT_NNZ, 0);
    hist_kernel<<<(ADJ_NNZ  + T - 1) / T, T>>>(adj_rows,  ADJ_NNZ,  1);

    scan_p1_kernel<<<NBLK, TILE>>>(0);
    scan_p1_kernel<<<NBLK, TILE>>>(1);
    scan_p2_kernel<<<1, 128>>>(0);
    scan_p2_kernel<<<1, 128>>>(1);
    scan_p3_kernel<<<NBLK, TILE>>>(0);
    scan_p3_kernel<<<NBLK, TILE>>>(1);

    scatter_kernel<<<(FEAT_NNZ + T - 1) / T, T>>>(feat_vals, feat_rows, feat_cols,
                                                  FEAT_NNZ, 0);
    scatter_kernel<<<(ADJ_NNZ + T - 1) / T, T>>>(adj_vals, adj_rows, adj_cols,
                                                 ADJ_NNZ, 1);

    const int rows_grid = (N_NODES + 7) / 8;   // 8 warps/block, warp per row
    spmm1_csr_kernel<<<rows_grid, T>>>((const float4*)weights);
    spmm2_csr_kernel<<<rows_grid, T>>>(out4, (const float4*)bias_vec);
}

// round 5
// speedup vs baseline: 3.4973x; 1.2700x over previous
#include <cuda_runtime.h>
#include <cuda_fp16.h>

#define N_NODES  100000
#define IN_DIM   256
#define OUT_DIM  128
#define FEAT_NNZ 1000000
#define ADJ_NNZ  1600000

#define TILE      1024
#define NBLK      ((N_NODES + TILE - 1) / TILE)   // 98

// ---------------------------------------------------------------------------
// Scratch (__device__ globals; referenced ONLY from device code)
// ---------------------------------------------------------------------------
// XW stored as fp16: row = 128 halfs = 256 B. Lane owns 4 cols = one uint2.
__device__ uint2  g_xw2[(size_t)N_NODES * 32];            // 25.6 MB

__device__ int    g_feat_cnt [N_NODES];
__device__ int    g_feat_ptr [N_NODES + 1];
__device__ int    g_feat_next[N_NODES];
__device__ float2 g_feat_csr [FEAT_NNZ];                  // {val, col bits}
__device__ int    g_feat_bsum[NBLK];
__device__ int    g_feat_boff[NBLK];

__device__ int    g_adj_cnt [N_NODES];
__device__ int    g_adj_ptr [N_NODES + 1];
__device__ int    g_adj_next[N_NODES];
__device__ float2 g_adj_csr [ADJ_NNZ];
__device__ int    g_adj_bsum[NBLK];
__device__ int    g_adj_boff[NBLK];

// ---------------------------------------------------------------------------
// 1. Zero the two histogram arrays (800 KB).
// ---------------------------------------------------------------------------
__global__ void zero_counters_kernel() {
    int i = blockIdx.x * blockDim.x + threadIdx.x;
    if (i < N_NODES) {
        g_feat_cnt[i] = 0;
        g_adj_cnt[i]  = 0;
    }
}

// ---------------------------------------------------------------------------
// 2. Fused row histogram: blocks [0, FB) do feat, blocks [FB, FB+AB) do adj.
// ---------------------------------------------------------------------------
__global__ void hist_both_kernel(const int* __restrict__ feat_rows,
                                 const int* __restrict__ adj_rows,
                                 int feat_blocks) {
    if (blockIdx.x < feat_blocks) {
        int i = blockIdx.x * blockDim.x + threadIdx.x;
        if (i < FEAT_NNZ) atomicAdd(&g_feat_cnt[feat_rows[i]], 1);
    } else {
        int i = (blockIdx.x - feat_blocks) * blockDim.x + threadIdx.x;
        if (i < ADJ_NNZ) atomicAdd(&g_adj_cnt[adj_rows[i]], 1);
    }
}

// ---------------------------------------------------------------------------
// 3a. Scan phase 1 (fused): 2*NBLK blocks; first NBLK = feat, rest = adj.
// ---------------------------------------------------------------------------
__global__ void scan_p1_kernel() {
    int which = (blockIdx.x >= NBLK);
    int blk   = which ? (blockIdx.x - NBLK) : blockIdx.x;
    const int* __restrict__ cnt = which ? g_adj_cnt  : g_feat_cnt;
    int* __restrict__ bsum      = which ? g_adj_bsum : g_feat_bsum;

    __shared__ int s[TILE];
    int t   = threadIdx.x;
    int idx = blk * TILE + t;
    s[t] = (idx < N_NODES) ? cnt[idx] : 0;
    __syncthreads();
    for (int off = TILE >> 1; off > 0; off >>= 1) {
        if (t < off) s[t] += s[t + off];
        __syncthreads();
    }
    if (t == 0) bsum[blk] = s[0];
}

// ---------------------------------------------------------------------------
// 3b. Scan phase 2 (fused): one block, 256 threads. Threads [0,128) scan the
//     feat tile sums, [128,256) scan the adj tile sums (independent groups).
// ---------------------------------------------------------------------------
__global__ void scan_p2_kernel() {
    __shared__ int s[256];
    int t = threadIdx.x;
    int which = t >> 7;           // 0 = feat, 1 = adj
    int u = t & 127;              // index within group
    const int* __restrict__ bsum = which ? g_adj_bsum : g_feat_bsum;
    int* __restrict__ boff       = which ? g_adj_boff : g_feat_boff;
    int* __restrict__ ptr        = which ? g_adj_ptr  : g_feat_ptr;

    int v = (u < NBLK) ? bsum[u] : 0;
    s[t] = v;
    __syncthreads();
    for (int off = 1; off < 128; off <<= 1) {
        int w = (u >= off) ? s[t - off] : 0;
        __syncthreads();
        s[t] += w;
        __syncthreads();
    }
    if (u < NBLK) boff[u] = s[t] - v;             // exclusive
    if (u == NBLK - 1) ptr[N_NODES] = s[t];       // total nnz
}

// ---------------------------------------------------------------------------
// 3c. Scan phase 3 (fused): per-tile inclusive scan + tile offset.
// ---------------------------------------------------------------------------
__global__ void scan_p3_kernel() {
    int which = (blockIdx.x >= NBLK);
    int blk   = which ? (blockIdx.x - NBLK) : blockIdx.x;
    const int* __restrict__ cnt  = which ? g_adj_cnt  : g_feat_cnt;
    const int* __restrict__ boff = which ? g_adj_boff : g_feat_boff;
    int* __restrict__ ptr        = which ? g_adj_ptr  : g_feat_ptr;
    int* __restrict__ next       = which ? g_adj_next : g_feat_next;

    __shared__ int s[TILE];
    int t   = threadIdx.x;
    int idx = blk * TILE + t;
    int v   = (idx < N_NODES) ? cnt[idx] : 0;
    s[t] = v;
    __syncthreads();
    for (int off = 1; off < TILE; off <<= 1) {
        int u = (t >= off) ? s[t - off] : 0;
        __syncthreads();
        s[t] += u;
        __syncthreads();
    }
    if (idx < N_NODES) {
        int excl = boff[blk] + s[t] - v;
        ptr[idx]  = excl;
        next[idx] = excl;
    }
}

// ---------------------------------------------------------------------------
// 4. Fused scatter: blocks [0, FB) feat, [FB, FB+AB) adj.
// ---------------------------------------------------------------------------
__global__ void scatter_both_kernel(const float* __restrict__ feat_vals,
                                    const int*   __restrict__ feat_rows,
                                    const int*   __restrict__ feat_cols,
                                    const float* __restrict__ adj_vals,
                                    const int*   __restrict__ adj_rows,
                                    const int*   __restrict__ adj_cols,
                                    int feat_blocks) {
    if (blockIdx.x < feat_blocks) {
        int i = blockIdx.x * blockDim.x + threadIdx.x;
        if (i >= FEAT_NNZ) return;
        int pos = atomicAdd(&g_feat_next[feat_rows[i]], 1);
        g_feat_csr[pos] = make_float2(feat_vals[i], __int_as_float(feat_cols[i]));
    } else {
        int i = (blockIdx.x - feat_blocks) * blockDim.x + threadIdx.x;
        if (i >= ADJ_NNZ) return;
        int pos = atomicAdd(&g_adj_next[adj_rows[i]], 1);
        g_adj_csr[pos] = make_float2(adj_vals[i], __int_as_float(adj_cols[i]));
    }
}

// ---------------------------------------------------------------------------
// 5. SpMM1 (CSR gather): XW[row,:] = sum_e val_e * W[col_e,:]
//    Warp per row; lane owns 4 OUT cols. fp32 accumulate, fp16 store.
// ---------------------------------------------------------------------------
__global__ void spmm1_csr_kernel(const float4* __restrict__ W4) {
    int row  = blockIdx.x * (blockDim.x >> 5) + (threadIdx.x >> 5);
    if (row >= N_NODES) return;
    int lane = threadIdx.x & 31;

    int s = g_feat_ptr[row];
    int e = g_feat_ptr[row + 1];

    float4 acc = make_float4(0.f, 0.f, 0.f, 0.f);
    for (int j = s; j < e; j++) {
        float2 vc = __ldg(&g_feat_csr[j]);          // uniform across warp
        float v = vc.x;
        int   c = __float_as_int(vc.y);
        float4 w = __ldg(&W4[(size_t)c * 32 + lane]);
        acc.x += v * w.x;
        acc.y += v * w.y;
        acc.z += v * w.z;
        acc.w += v * w.w;
    }
    __half2 h0 = __floats2half2_rn(acc.x, acc.y);
    __half2 h1 = __floats2half2_rn(acc.z, acc.w);
    uint2 packed;
    packed.x = *reinterpret_cast<unsigned int*>(&h0);
    packed.y = *reinterpret_cast<unsigned int*>(&h1);
    g_xw2[(size_t)row * 32 + lane] = packed;
}

// ---------------------------------------------------------------------------
// 6. SpMM2 (CSR gather, fp16 XW) + fused bias + ReLU.
//    Gather traffic halved: 256 B/row instead of 512 B.
// ---------------------------------------------------------------------------
__global__ void spmm2_csr_kernel(float4* __restrict__ out4,
                                 const float4* __restrict__ bias4) {
    int row  = blockIdx.x * (blockDim.x >> 5) + (threadIdx.x >> 5);
    if (row >= N_NODES) return;
    int lane = threadIdx.x & 31;

    int s = g_adj_ptr[row];
    int e = g_adj_ptr[row + 1];

    float4 acc = make_float4(0.f, 0.f, 0.f, 0.f);
    for (int j = s; j < e; j++) {
        float2 vc = __ldg(&g_adj_csr[j]);           // uniform across warp
        float v = vc.x;
        int   c = __float_as_int(vc.y);
        uint2 raw = __ldg(&g_xw2[(size_t)c * 32 + lane]);
        float2 f0 = __half22float2(*reinterpret_cast<__half2*>(&raw.x));
        float2 f1 = __half22float2(*reinterpret_cast<__half2*>(&raw.y));
        acc.x += v * f0.x;
        acc.y += v * f0.y;
        acc.z += v * f1.x;
        acc.w += v * f1.y;
    }

    float4 b = __ldg(&bias4[lane]);
    acc.x = fmaxf(acc.x + b.x, 0.f);
    acc.y = fmaxf(acc.y + b.y, 0.f);
    acc.z = fmaxf(acc.z + b.z, 0.f);
    acc.w = fmaxf(acc.w + b.w, 0.f);
    out4[(size_t)row * 32 + lane] = acc;
}

// ---------------------------------------------------------------------------
extern "C" void kernel_launch(void* const* d_in, const int* in_sizes, int n_in,
                              void* d_out, int out_size) {
    const float* feat_vals = (const float*)d_in[0];
    const int*   feat_rows = (const int*)  d_in[1];
    const int*   feat_cols = (const int*)  d_in[2];
    const float* adj_vals  = (const float*)d_in[3];
    const int*   adj_rows  = (const int*)  d_in[4];
    const int*   adj_cols  = (const int*)  d_in[5];
    const float* weights   = (const float*)d_in[6];
    const float* bias_vec  = (const float*)d_in[7];
    float4* out4 = (float4*)d_out;

    const int T = 256;
    const int FB = (FEAT_NNZ + T - 1) / T;
    const int AB = (ADJ_NNZ  + T - 1) / T;

    zero_counters_kernel<<<(N_NODES + T - 1) / T, T>>>();

    hist_both_kernel<<<FB + AB, T>>>(feat_rows, adj_rows, FB);

    scan_p1_kernel<<<2 * NBLK, TILE>>>();
    scan_p2_kernel<<<1, 256>>>();
    scan_p3_kernel<<<2 * NBLK, TILE>>>();

    scatter_both_kernel<<<FB + AB, T>>>(feat_vals, feat_rows, feat_cols,
                                        adj_vals, adj_rows, adj_cols, FB);

    const int rows_grid = (N_NODES + 7) / 8;   // 8 warps/block, warp per row
    spmm1_csr_kernel<<<rows_grid, T>>>((const float4*)weights);
    spmm2_csr_kernel<<<rows_grid, T>>>(out4, (const float4*)bias_vec);
}

// round 7
// speedup vs baseline: 3.5528x; 1.0159x over previous
#include <cuda_runtime.h>
#include <cuda_fp16.h>

#define N_NODES  100000
#define IN_DIM   256
#define OUT_DIM  128
#define FEAT_NNZ 1000000
#define ADJ_NNZ  1600000

#define TILE      1024
#define NBLK      ((N_NODES + TILE - 1) / TILE)   // 98

// ---------------------------------------------------------------------------
// Scratch (__device__ globals; zero-initialized at module load; referenced
// ONLY from device code). cnt arrays are re-zeroed by scan_p3 after use so
// every graph replay sees the same initial state.
// ---------------------------------------------------------------------------
__device__ uint2  g_xw2[(size_t)N_NODES * 32];            // XW fp16, 25.6 MB

__device__ int    g_feat_cnt [N_NODES];
__device__ int    g_feat_ptr [N_NODES + 1];
__device__ int    g_feat_next[N_NODES];
__device__ float2 g_feat_csr [FEAT_NNZ];                  // {val, col bits}
__device__ int    g_feat_bsum[NBLK];

__device__ int    g_adj_cnt [N_NODES];
__device__ int    g_adj_ptr [N_NODES + 1];
__device__ int    g_adj_next[N_NODES];
__device__ float2 g_adj_csr [ADJ_NNZ];
__device__ int    g_adj_bsum[NBLK];

// ---------------------------------------------------------------------------
// 1. Fused row histogram: blocks [0, FB) do feat, blocks [FB, FB+AB) do adj.
//    cnt arrays are guaranteed zero on entry (static init / p3 restore).
// ---------------------------------------------------------------------------
__global__ void hist_both_kernel(const int* __restrict__ feat_rows,
                                 const int* __restrict__ adj_rows,
                                 int feat_blocks) {
    if (blockIdx.x < feat_blocks) {
        int i = blockIdx.x * blockDim.x + threadIdx.x;
        if (i < FEAT_NNZ) atomicAdd(&g_feat_cnt[feat_rows[i]], 1);
    } else {
        int i = (blockIdx.x - feat_blocks) * blockDim.x + threadIdx.x;
        if (i < ADJ_NNZ) atomicAdd(&g_adj_cnt[adj_rows[i]], 1);
    }
}

// ---------------------------------------------------------------------------
// 2a. Scan phase 1 (fused): 2*NBLK blocks; first NBLK = feat, rest = adj.
//     Per-tile sums of cnt.
// ---------------------------------------------------------------------------
__global__ void scan_p1_kernel() {
    int which = (blockIdx.x >= NBLK);
    int blk   = which ? (blockIdx.x - NBLK) : blockIdx.x;
    const int* __restrict__ cnt = which ? g_adj_cnt  : g_feat_cnt;
    int* __restrict__ bsum      = which ? g_adj_bsum : g_feat_bsum;

    __shared__ int s[TILE];
    int t   = threadIdx.x;
    int idx = blk * TILE + t;
    s[t] = (idx < N_NODES) ? cnt[idx] : 0;
    __syncthreads();
    for (int off = TILE >> 1; off > 0; off >>= 1) {
        if (t < off) s[t] += s[t + off];
        __syncthreads();
    }
    if (t == 0) bsum[blk] = s[0];
}

// ---------------------------------------------------------------------------
// 2b. Scan phase 3 (fused, self-offsetting): each block
//       (i)  reduces bsum[0..blk) to get its own tile offset (no p2 kernel),
//       (ii) inclusive-scans its 1024-tile of cnt,
//       (iii) writes ptr + next, zeroes cnt (restores replay invariant),
//       (iv) last tile writes ptr[N_NODES].
// ---------------------------------------------------------------------------
__global__ void scan_p3_kernel() {
    int which = (blockIdx.x >= NBLK);
    int blk   = which ? (blockIdx.x - NBLK) : blockIdx.x;
    int* __restrict__ cnt        = which ? g_adj_cnt  : g_feat_cnt;
    const int* __restrict__ bsum = which ? g_adj_bsum : g_feat_bsum;
    int* __restrict__ ptr        = which ? g_adj_ptr  : g_feat_ptr;
    int* __restrict__ next       = which ? g_adj_next : g_feat_next;

    __shared__ int s[TILE];
    __shared__ int red[128];

    int t = threadIdx.x;

    // (i) tile offset = sum of bsum[i] for i < blk  (masked block reduction)
    if (t < 128) {
        red[t] = (t < NBLK && t < blk) ? bsum[t] : 0;
    }
    __syncthreads();
    for (int off = 64; off > 0; off >>= 1) {
        if (t < off) red[t] += red[t + off];
        __syncthreads();
    }
    int boff = red[0];
    __syncthreads();

    // (ii) inclusive Hillis-Steele over this tile
    int idx = blk * TILE + t;
    int v   = (idx < N_NODES) ? cnt[idx] : 0;
    s[t] = v;
    __syncthreads();
    for (int off = 1; off < TILE; off <<= 1) {
        int u = (t >= off) ? s[t - off] : 0;
        __syncthreads();
        s[t] += u;
        __syncthreads();
    }

    // (iii) write outputs, restore cnt = 0
    if (idx < N_NODES) {
        int excl = boff + s[t] - v;
        ptr[idx]  = excl;
        next[idx] = excl;
        cnt[idx]  = 0;
    }

    // (iv) total nnz
    if (blk == NBLK - 1 && t == TILE - 1) {
        ptr[N_NODES] = boff + s[t];
    }
}

// ---------------------------------------------------------------------------
// 3. Fused scatter: blocks [0, FB) feat, [FB, FB+AB) adj.
// ---------------------------------------------------------------------------
__global__ void scatter_both_kernel(const float* __restrict__ feat_vals,
                                    const int*   __restrict__ feat_rows,
                                    const int*   __restrict__ feat_cols,
                                    const float* __restrict__ adj_vals,
                                    const int*   __restrict__ adj_rows,
                                    const int*   __restrict__ adj_cols,
                                    int feat_blocks) {
    if (blockIdx.x < feat_blocks) {
        int i = blockIdx.x * blockDim.x + threadIdx.x;
        if (i >= FEAT_NNZ) return;
        int pos = atomicAdd(&g_feat_next[feat_rows[i]], 1);
        g_feat_csr[pos] = make_float2(feat_vals[i], __int_as_float(feat_cols[i]));
    } else {
        int i = (blockIdx.x - feat_blocks) * blockDim.x + threadIdx.x;
        if (i >= ADJ_NNZ) return;
        int pos = atomicAdd(&g_adj_next[adj_rows[i]], 1);
        g_adj_csr[pos] = make_float2(adj_vals[i], __int_as_float(adj_cols[i]));
    }
}

// ---------------------------------------------------------------------------
// 4. SpMM1 (CSR gather): XW[row,:] = sum_e val_e * W[col_e,:]
//    Warp per row; lane owns 4 OUT cols. fp32 accumulate, fp16 store.
//    Unrolled x2 for load batching (W is L1-resident).
// ---------------------------------------------------------------------------
__global__ void spmm1_csr_kernel(const float4* __restrict__ W4) {
    int row  = blockIdx.x * (blockDim.x >> 5) + (threadIdx.x >> 5);
    if (row >= N_NODES) return;
    int lane = threadIdx.x & 31;

    int s = g_feat_ptr[row];
    int e = g_feat_ptr[row + 1];

    float4 acc = make_float4(0.f, 0.f, 0.f, 0.f);
    int j = s;
    for (; j + 2 <= e; j += 2) {
        float2 vc0 = __ldg(&g_feat_csr[j]);
        float2 vc1 = __ldg(&g_feat_csr[j + 1]);
        int c0 = __float_as_int(vc0.y);
        int c1 = __float_as_int(vc1.y);
        float4 w0 = __ldg(&W4[(size_t)c0 * 32 + lane]);
        float4 w1 = __ldg(&W4[(size_t)c1 * 32 + lane]);
        acc.x += vc0.x * w0.x + vc1.x * w1.x;
        acc.y += vc0.x * w0.y + vc1.x * w1.y;
        acc.z += vc0.x * w0.z + vc1.x * w1.z;
        acc.w += vc0.x * w0.w + vc1.x * w1.w;
    }
    for (; j < e; j++) {
        float2 vc = __ldg(&g_feat_csr[j]);
        int c = __float_as_int(vc.y);
        float4 w = __ldg(&W4[(size_t)c * 32 + lane]);
        acc.x += vc.x * w.x;
        acc.y += vc.x * w.y;
        acc.z += vc.x * w.z;
        acc.w += vc.x * w.w;
    }
    __half2 h0 = __floats2half2_rn(acc.x, acc.y);
    __half2 h1 = __floats2half2_rn(acc.z, acc.w);
    uint2 packed;
    packed.x = *reinterpret_cast<unsigned int*>(&h0);
    packed.y = *reinterpret_cast<unsigned int*>(&h1);
    g_xw2[(size_t)row * 32 + lane] = packed;
}

// ---------------------------------------------------------------------------
// 5. SpMM2 (CSR gather, fp16 XW) + fused bias + ReLU.
//    Unrolled x4: 4 independent row gathers in flight per warp (MLP=4).
// ---------------------------------------------------------------------------
__global__ void spmm2_csr_kernel(float4* __restrict__ out4,
                                 const float4* __restrict__ bias4) {
    int row  = blockIdx.x * (blockDim.x >> 5) + (threadIdx.x >> 5);
    if (row >= N_NODES) return;
    int lane = threadIdx.x & 31;

    int s = g_adj_ptr[row];
    int e = g_adj_ptr[row + 1];

    float4 acc = make_float4(0.f, 0.f, 0.f, 0.f);
    int j = s;
    for (; j + 4 <= e; j += 4) {
        float2 vc0 = __ldg(&g_adj_csr[j]);
        float2 vc1 = __ldg(&g_adj_csr[j + 1]);
        float2 vc2 = __ldg(&g_adj_csr[j + 2]);
        float2 vc3 = __ldg(&g_adj_csr[j + 3]);
        uint2 r0 = __ldg(&g_xw2[(size_t)__float_as_int(vc0.y) * 32 + lane]);
        uint2 r1 = __ldg(&g_xw2[(size_t)__float_as_int(vc1.y) * 32 + lane]);
        uint2 r2 = __ldg(&g_xw2[(size_t)__float_as_int(vc2.y) * 32 + lane]);
        uint2 r3 = __ldg(&g_xw2[(size_t)__float_as_int(vc3.y) * 32 + lane]);
        float2 a0 = __half22float2(*reinterpret_cast<__half2*>(&r0.x));
        float2 b0 = __half22float2(*reinterpret_cast<__half2*>(&r0.y));
        float2 a1 = __half22float2(*reinterpret_cast<__half2*>(&r1.x));
        float2 b1 = __half22float2(*reinterpret_cast<__half2*>(&r1.y));
        float2 a2 = __half22float2(*reinterpret_cast<__half2*>(&r2.x));
        float2 b2 = __half22float2(*reinterpret_cast<__half2*>(&r2.y));
        float2 a3 = __half22float2(*reinterpret_cast<__half2*>(&r3.x));
        float2 b3 = __half22float2(*reinterpret_cast<__half2*>(&r3.y));
        acc.x += vc0.x * a0.x + vc1.x * a1.x + vc2.x * a2.x + vc3.x * a3.x;
        acc.y += vc0.x * a0.y + vc1.x * a1.y + vc2.x * a2.y + vc3.x * a3.y;
        acc.z += vc0.x * b0.x + vc1.x * b1.x + vc2.x * b2.x + vc3.x * b3.x;
        acc.w += vc0.x * b0.y + vc1.x * b1.y + vc2.x * b2.y + vc3.x * b3.y;
    }
    for (; j < e; j++) {
        float2 vc = __ldg(&g_adj_csr[j]);
        uint2 raw = __ldg(&g_xw2[(size_t)__float_as_int(vc.y) * 32 + lane]);
        float2 f0 = __half22float2(*reinterpret_cast<__half2*>(&raw.x));
        float2 f1 = __half22float2(*reinterpret_cast<__half2*>(&raw.y));
        acc.x += vc.x * f0.x;
        acc.y += vc.x * f0.y;
        acc.z += vc.x * f1.x;
        acc.w += vc.x * f1.y;
    }

    float4 b = __ldg(&bias4[lane]);
    acc.x = fmaxf(acc.x + b.x, 0.f);
    acc.y = fmaxf(acc.y + b.y, 0.f);
    acc.z = fmaxf(acc.z + b.z, 0.f);
    acc.w = fmaxf(acc.w + b.w, 0.f);
    out4[(size_t)row * 32 + lane] = acc;
}

// ---------------------------------------------------------------------------
extern "C" void kernel_launch(void* const* d_in, const int* in_sizes, int n_in,
                              void* d_out, int out_size) {
    const float* feat_vals = (const float*)d_in[0];
    const int*   feat_rows = (const int*)  d_in[1];
    const int*   feat_cols = (const int*)  d_in[2];
    const float* adj_vals  = (const float*)d_in[3];
    const int*   adj_rows  = (const int*)  d_in[4];
    const int*   adj_cols  = (const int*)  d_in[5];
    const float* weights   = (const float*)d_in[6];
    const float* bias_vec  = (const float*)d_in[7];
    float4* out4 = (float4*)d_out;

    const int T = 256;
    const int FB = (FEAT_NNZ + T - 1) / T;
    const int AB = (ADJ_NNZ  + T - 1) / T;

    hist_both_kernel<<<FB + AB, T>>>(feat_rows, adj_rows, FB);

    scan_p1_kernel<<<2 * NBLK, TILE>>>();
    scan_p3_kernel<<<2 * NBLK, TILE>>>();

    scatter_both_kernel<<<FB + AB, T>>>(feat_vals, feat_rows, feat_cols,
                                        adj_vals, adj_rows, adj_cols, FB);

    const int rows_grid = (N_NODES + 7) / 8;   // 8 warps/block, warp per row
    spmm1_csr_kernel<<<rows_grid, T>>>((const float4*)weights);
    spmm2_csr_kernel<<<rows_grid, T>>>(out4, (const float4*)bias_vec);
}

// round 8
// speedup vs baseline: 3.5811x; 1.0080x over previous
#include <cuda_runtime.h>
#include <cuda_fp16.h>

#define N_NODES  100000
#define IN_DIM   256
#define OUT_DIM  128
#define FEAT_NNZ 1000000
#define ADJ_NNZ  1600000

#define TILE      1024
#define NBLK      ((N_NODES + TILE - 1) / TILE)   // 98

// ---------------------------------------------------------------------------
// Scratch (__device__ globals; zero-initialized at module load; referenced
// ONLY from device code). cnt arrays are re-zeroed by scan_p3 after use so
// every graph replay sees the same initial state.
// ---------------------------------------------------------------------------
__device__ uint2  g_xw2[(size_t)N_NODES * 32];            // XW fp16, 25.6 MB

__device__ int    g_feat_cnt [N_NODES];
__device__ int    g_feat_ptr [N_NODES + 1];
__device__ int    g_feat_rank[FEAT_NNZ];                  // within-row rank
__device__ float2 g_feat_csr [FEAT_NNZ];                  // {val, col bits}
__device__ int    g_feat_bsum[NBLK];

__device__ int    g_adj_cnt [N_NODES];
__device__ int    g_adj_ptr [N_NODES + 1];
__device__ int    g_adj_rank[ADJ_NNZ];
__device__ float2 g_adj_csr [ADJ_NNZ];
__device__ int    g_adj_bsum[NBLK];

// ---------------------------------------------------------------------------
// 1. Fused row histogram, capturing each entry's within-row rank (the value
//    the atomic returns). This removes ALL atomics from the scatter pass.
// ---------------------------------------------------------------------------
__global__ void hist_both_kernel(const int* __restrict__ feat_rows,
                                 const int* __restrict__ adj_rows,
                                 int feat_blocks) {
    if (blockIdx.x < feat_blocks) {
        int i = blockIdx.x * blockDim.x + threadIdx.x;
        if (i < FEAT_NNZ)
            g_feat_rank[i] = atomicAdd(&g_feat_cnt[feat_rows[i]], 1);
    } else {
        int i = (blockIdx.x - feat_blocks) * blockDim.x + threadIdx.x;
        if (i < ADJ_NNZ)
            g_adj_rank[i] = atomicAdd(&g_adj_cnt[adj_rows[i]], 1);
    }
}

// ---------------------------------------------------------------------------
// 2a. Scan phase 1 (fused): per-tile sums of cnt. First NBLK blocks = feat.
// ---------------------------------------------------------------------------
__global__ void scan_p1_kernel() {
    int which = (blockIdx.x >= NBLK);
    int blk   = which ? (blockIdx.x - NBLK) : blockIdx.x;
    const int* __restrict__ cnt = which ? g_adj_cnt  : g_feat_cnt;
    int* __restrict__ bsum      = which ? g_adj_bsum : g_feat_bsum;

    __shared__ int s[TILE];
    int t   = threadIdx.x;
    int idx = blk * TILE + t;
    s[t] = (idx < N_NODES) ? cnt[idx] : 0;
    __syncthreads();
    for (int off = TILE >> 1; off > 0; off >>= 1) {
        if (t < off) s[t] += s[t + off];
        __syncthreads();
    }
    if (t == 0) bsum[blk] = s[0];
}

// ---------------------------------------------------------------------------
// 2b. Scan phase 3 (fused, self-offsetting): each block
//       (i)  reduces bsum[0..blk) for its tile offset,
//       (ii) inclusive-scans its 1024-tile of cnt,
//       (iii) writes ptr, zeroes cnt (restores the replay invariant),
//       (iv) last tile writes ptr[N_NODES].
// ---------------------------------------------------------------------------
__global__ void scan_p3_kernel() {
    int which = (blockIdx.x >= NBLK);
    int blk   = which ? (blockIdx.x - NBLK) : blockIdx.x;
    int* __restrict__ cnt        = which ? g_adj_cnt  : g_feat_cnt;
    const int* __restrict__ bsum = which ? g_adj_bsum : g_feat_bsum;
    int* __restrict__ ptr        = which ? g_adj_ptr  : g_feat_ptr;

    __shared__ int s[TILE];
    __shared__ int red[128];

    int t = threadIdx.x;

    // (i) tile offset = sum of bsum[i] for i < blk
    if (t < 128) {
        red[t] = (t < NBLK && t < blk) ? bsum[t] : 0;
    }
    __syncthreads();
    for (int off = 64; off > 0; off >>= 1) {
        if (t < off) red[t] += red[t + off];
        __syncthreads();
    }
    int boff = red[0];
    __syncthreads();

    // (ii) inclusive Hillis-Steele over this tile
    int idx = blk * TILE + t;
    int v   = (idx < N_NODES) ? cnt[idx] : 0;
    s[t] = v;
    __syncthreads();
    for (int off = 1; off < TILE; off <<= 1) {
        int u = (t >= off) ? s[t - off] : 0;
        __syncthreads();
        s[t] += u;
        __syncthreads();
    }

    // (iii) write ptr, restore cnt = 0
    if (idx < N_NODES) {
        ptr[idx] = boff + s[t] - v;
        cnt[idx] = 0;
    }

    // (iv) total nnz
    if (blk == NBLK - 1 && t == TILE - 1) {
        ptr[N_NODES] = boff + s[t];
    }
}

// ---------------------------------------------------------------------------
// 3. Fused scatter — NO atomics: pos = ptr[row] + precomputed rank.
//    Pure load/store; fully latency-overlappable.
// ---------------------------------------------------------------------------
__global__ void scatter_both_kernel(const float* __restrict__ feat_vals,
                                    const int*   __restrict__ feat_rows,
                                    const int*   __restrict__ feat_cols,
                                    const float* __restrict__ adj_vals,
                                    const int*   __restrict__ adj_rows,
                                    const int*   __restrict__ adj_cols,
                                    int feat_blocks) {
    if (blockIdx.x < feat_blocks) {
        int i = blockIdx.x * blockDim.x + threadIdx.x;
        if (i >= FEAT_NNZ) return;
        int pos = __ldg(&g_feat_ptr[feat_rows[i]]) + g_feat_rank[i];
        g_feat_csr[pos] = make_float2(feat_vals[i], __int_as_float(feat_cols[i]));
    } else {
        int i = (blockIdx.x - feat_blocks) * blockDim.x + threadIdx.x;
        if (i >= ADJ_NNZ) return;
        int pos = __ldg(&g_adj_ptr[adj_rows[i]]) + g_adj_rank[i];
        g_adj_csr[pos] = make_float2(adj_vals[i], __int_as_float(adj_cols[i]));
    }
}

// ---------------------------------------------------------------------------
// 4. SpMM1 (CSR gather): XW[row,:] = sum_e val_e * W[col_e,:]
//    Warp per row; lane owns 4 OUT cols. fp32 accumulate, fp16 store.
// ---------------------------------------------------------------------------
__global__ void spmm1_csr_kernel(const float4* __restrict__ W4) {
    int row  = blockIdx.x * (blockDim.x >> 5) + (threadIdx.x >> 5);
    if (row >= N_NODES) return;
    int lane = threadIdx.x & 31;

    int s = g_feat_ptr[row];
    int e = g_feat_ptr[row + 1];

    float4 acc = make_float4(0.f, 0.f, 0.f, 0.f);
    int j = s;
    for (; j + 2 <= e; j += 2) {
        float2 vc0 = __ldg(&g_feat_csr[j]);
        float2 vc1 = __ldg(&g_feat_csr[j + 1]);
        int c0 = __float_as_int(vc0.y);
        int c1 = __float_as_int(vc1.y);
        float4 w0 = __ldg(&W4[(size_t)c0 * 32 + lane]);
        float4 w1 = __ldg(&W4[(size_t)c1 * 32 + lane]);
        acc.x += vc0.x * w0.x + vc1.x * w1.x;
        acc.y += vc0.x * w0.y + vc1.x * w1.y;
        acc.z += vc0.x * w0.z + vc1.x * w1.z;
        acc.w += vc0.x * w0.w + vc1.x * w1.w;
    }
    for (; j < e; j++) {
        float2 vc = __ldg(&g_feat_csr[j]);
        int c = __float_as_int(vc.y);
        float4 w = __ldg(&W4[(size_t)c * 32 + lane]);
        acc.x += vc.x * w.x;
        acc.y += vc.x * w.y;
        acc.z += vc.x * w.z;
        acc.w += vc.x * w.w;
    }
    __half2 h0 = __floats2half2_rn(acc.x, acc.y);
    __half2 h1 = __floats2half2_rn(acc.z, acc.w);
    uint2 packed;
    packed.x = *reinterpret_cast<unsigned int*>(&h0);
    packed.y = *reinterpret_cast<unsigned int*>(&h1);
    g_xw2[(size_t)row * 32 + lane] = packed;
}

// ---------------------------------------------------------------------------
// 5. SpMM2 (CSR gather, fp16 XW) + fused bias + ReLU. Unrolled x4 (MLP=4).
// ---------------------------------------------------------------------------
__global__ void spmm2_csr_kernel(float4* __restrict__ out4,
                                 const float4* __restrict__ bias4) {
    int row  = blockIdx.x * (blockDim.x >> 5) + (threadIdx.x >> 5);
    if (row >= N_NODES) return;
    int lane = threadIdx.x & 31;

    int s = g_adj_ptr[row];
    int e = g_adj_ptr[row + 1];

    float4 acc = make_float4(0.f, 0.f, 0.f, 0.f);
    int j = s;
    for (; j + 4 <= e; j += 4) {
        float2 vc0 = __ldg(&g_adj_csr[j]);
        float2 vc1 = __ldg(&g_adj_csr[j + 1]);
        float2 vc2 = __ldg(&g_adj_csr[j + 2]);
        float2 vc3 = __ldg(&g_adj_csr[j + 3]);
        uint2 r0 = __ldg(&g_xw2[(size_t)__float_as_int(vc0.y) * 32 + lane]);
        uint2 r1 = __ldg(&g_xw2[(size_t)__float_as_int(vc1.y) * 32 + lane]);
        uint2 r2 = __ldg(&g_xw2[(size_t)__float_as_int(vc2.y) * 32 + lane]);
        uint2 r3 = __ldg(&g_xw2[(size_t)__float_as_int(vc3.y) * 32 + lane]);
        float2 a0 = __half22float2(*reinterpret_cast<__half2*>(&r0.x));
        float2 b0 = __half22float2(*reinterpret_cast<__half2*>(&r0.y));
        float2 a1 = __half22float2(*reinterpret_cast<__half2*>(&r1.x));
        float2 b1 = __half22float2(*reinterpret_cast<__half2*>(&r1.y));
        float2 a2 = __half22float2(*reinterpret_cast<__half2*>(&r2.x));
        float2 b2 = __half22float2(*reinterpret_cast<__half2*>(&r2.y));
        float2 a3 = __half22float2(*reinterpret_cast<__half2*>(&r3.x));
        float2 b3 = __half22float2(*reinterpret_cast<__half2*>(&r3.y));
        acc.x += vc0.x * a0.x + vc1.x * a1.x + vc2.x * a2.x + vc3.x * a3.x;
        acc.y += vc0.x * a0.y + vc1.x * a1.y + vc2.x * a2.y + vc3.x * a3.y;
        acc.z += vc0.x * b0.x + vc1.x * b1.x + vc2.x * b2.x + vc3.x * b3.x;
        acc.w += vc0.x * b0.y + vc1.x * b1.y + vc2.x * b2.y + vc3.x * b3.y;
    }
    for (; j < e; j++) {
        float2 vc = __ldg(&g_adj_csr[j]);
        uint2 raw = __ldg(&g_xw2[(size_t)__float_as_int(vc.y) * 32 + lane]);
        float2 f0 = __half22float2(*reinterpret_cast<__half2*>(&raw.x));
        float2 f1 = __half22float2(*reinterpret_cast<__half2*>(&raw.y));
        acc.x += vc.x * f0.x;
        acc.y += vc.x * f0.y;
        acc.z += vc.x * f1.x;
        acc.w += vc.x * f1.y;
    }

    float4 b = __ldg(&bias4[lane]);
    acc.x = fmaxf(acc.x + b.x, 0.f);
    acc.y = fmaxf(acc.y + b.y, 0.f);
    acc.z = fmaxf(acc.z + b.z, 0.f);
    acc.w = fmaxf(acc.w + b.w, 0.f);
    out4[(size_t)row * 32 + lane] = acc;
}

// ---------------------------------------------------------------------------
extern "C" void kernel_launch(void* const* d_in, const int* in_sizes, int n_in,
                              void* d_out, int out_size) {
    const float* feat_vals = (const float*)d_in[0];
    const int*   feat_rows = (const int*)  d_in[1];
    const int*   feat_cols = (const int*)  d_in[2];
    const float* adj_vals  = (const float*)d_in[3];
    const int*   adj_rows  = (const int*)  d_in[4];
    const int*   adj_cols  = (const int*)  d_in[5];
    const float* weights   = (const float*)d_in[6];
    const float* bias_vec  = (const float*)d_in[7];
    float4* out4 = (float4*)d_out;

    const int T = 256;
    const int FB = (FEAT_NNZ + T - 1) / T;
    const int AB = (ADJ_NNZ  + T - 1) / T;

    hist_both_kernel<<<FB + AB, T>>>(feat_rows, adj_rows, FB);

    scan_p1_kernel<<<2 * NBLK, TILE>>>();
    scan_p3_kernel<<<2 * NBLK, TILE>>>();

    scatter_both_kernel<<<FB + AB, T>>>(feat_vals, feat_rows, feat_cols,
                                        adj_vals, adj_rows, adj_cols, FB);

    const int rows_grid = (N_NODES + 7) / 8;   // 8 warps/block, warp per row
    spmm1_csr_kernel<<<rows_grid, T>>>((const float4*)weights);
    spmm2_csr_kernel<<<rows_grid, T>>>(out4, (const float4*)bias_vec);
}

// round 9
// speedup vs baseline: 3.6580x; 1.0215x over previous
#include <cuda_runtime.h>
#include <cuda_fp16.h>

#define N_NODES  100000
#define IN_DIM   256
#define OUT_DIM  128
#define FEAT_NNZ 1000000
#define ADJ_NNZ  1600000

#define TILE      1024
#define NBLK      ((N_NODES + TILE - 1) / TILE)   // 98

#define T         256
#define FB        ((FEAT_NNZ + T - 1) / T)        // 3907 feat scatter blocks
#define AB        ((ADJ_NNZ  + T - 1) / T)        // 6250 adj scatter blocks
#define ROWS_GRID ((N_NODES + 7) / 8)             // 12500 spmm row blocks

// ---------------------------------------------------------------------------
// Scratch (__device__ globals; zero-initialized at module load; referenced
// ONLY from device code). cnt arrays are re-zeroed by scan_p3 after use so
// every graph replay sees the same initial state.
// ---------------------------------------------------------------------------
__device__ uint2  g_xw2[(size_t)N_NODES * 32];            // XW fp16, 25.6 MB

__device__ int    g_feat_cnt [N_NODES];
__device__ int    g_feat_ptr [N_NODES + 1];
__device__ int    g_feat_rank[FEAT_NNZ];                  // within-row rank
__device__ float2 g_feat_csr [FEAT_NNZ];                  // {val, col bits}
__device__ int    g_feat_bsum[NBLK];

__device__ int    g_adj_cnt [N_NODES];
__device__ int    g_adj_ptr [N_NODES + 1];
__device__ int    g_adj_rank[ADJ_NNZ];
__device__ float2 g_adj_csr [ADJ_NNZ];
__device__ int    g_adj_bsum[NBLK];

// ---------------------------------------------------------------------------
// 1. Fused row histogram, capturing each entry's within-row rank (the value
//    the atomic returns). Scatter then needs NO atomics.
// ---------------------------------------------------------------------------
__global__ void hist_both_kernel(const int* __restrict__ feat_rows,
                                 const int* __restrict__ adj_rows) {
    if (blockIdx.x < FB) {
        int i = blockIdx.x * T + threadIdx.x;
        if (i < FEAT_NNZ)
            g_feat_rank[i] = atomicAdd(&g_feat_cnt[feat_rows[i]], 1);
    } else {
        int i = (blockIdx.x - FB) * T + threadIdx.x;
        if (i < ADJ_NNZ)
            g_adj_rank[i] = atomicAdd(&g_adj_cnt[adj_rows[i]], 1);
    }
}

// ---------------------------------------------------------------------------
// 2a. Scan phase 1 (fused): per-tile sums of cnt. First NBLK blocks = feat.
// ---------------------------------------------------------------------------
__global__ void scan_p1_kernel() {
    int which = (blockIdx.x >= NBLK);
    int blk   = which ? (blockIdx.x - NBLK) : blockIdx.x;
    const int* __restrict__ cnt = which ? g_adj_cnt  : g_feat_cnt;
    int* __restrict__ bsum      = which ? g_adj_bsum : g_feat_bsum;

    __shared__ int s[TILE];
    int t   = threadIdx.x;
    int idx = blk * TILE + t;
    s[t] = (idx < N_NODES) ? cnt[idx] : 0;
    __syncthreads();
    for (int off = TILE >> 1; off > 0; off >>= 1) {
        if (t < off) s[t] += s[t + off];
        __syncthreads();
    }
    if (t == 0) bsum[blk] = s[0];
}

// ---------------------------------------------------------------------------
// 2b. Scan phase 3 (fused, self-offsetting): each block
//       (i)  reduces bsum[0..blk) for its tile offset,
//       (ii) inclusive-scans its 1024-tile of cnt,
//       (iii) writes ptr, zeroes cnt (restores the replay invariant),
//       (iv) last tile writes ptr[N_NODES].
// ---------------------------------------------------------------------------
__global__ void scan_p3_kernel() {
    int which = (blockIdx.x >= NBLK);
    int blk   = which ? (blockIdx.x - NBLK) : blockIdx.x;
    int* __restrict__ cnt        = which ? g_adj_cnt  : g_feat_cnt;
    const int* __restrict__ bsum = which ? g_adj_bsum : g_feat_bsum;
    int* __restrict__ ptr        = which ? g_adj_ptr  : g_feat_ptr;

    __shared__ int s[TILE];
    __shared__ int red[128];

    int t = threadIdx.x;

    // (i) tile offset = sum of bsum[i] for i < blk
    if (t < 128) {
        red[t] = (t < NBLK && t < blk) ? bsum[t] : 0;
    }
    __syncthreads();
    for (int off = 64; off > 0; off >>= 1) {
        if (t < off) red[t] += red[t + off];
        __syncthreads();
    }
    int boff = red[0];
    __syncthreads();

    // (ii) inclusive Hillis-Steele over this tile
    int idx = blk * TILE + t;
    int v   = (idx < N_NODES) ? cnt[idx] : 0;
    s[t] = v;
    __syncthreads();
    for (int off = 1; off < TILE; off <<= 1) {
        int u = (t >= off) ? s[t - off] : 0;
        __syncthreads();
        s[t] += u;
        __syncthreads();
    }

    // (iii) write ptr, restore cnt = 0
    if (idx < N_NODES) {
        ptr[idx] = boff + s[t] - v;
        cnt[idx] = 0;
    }

    // (iv) total nnz
    if (blk == NBLK - 1 && t == TILE - 1) {
        ptr[N_NODES] = boff + s[t];
    }
}

// ---------------------------------------------------------------------------
// 3. Feat scatter — no atomics: pos = ptr[row] + precomputed rank.
// ---------------------------------------------------------------------------
__global__ void scatter_feat_kernel(const float* __restrict__ feat_vals,
                                    const int*   __restrict__ feat_rows,
                                    const int*   __restrict__ feat_cols) {
    int i = blockIdx.x * T + threadIdx.x;
    if (i >= FEAT_NNZ) return;
    int pos = __ldg(&g_feat_ptr[feat_rows[i]]) + g_feat_rank[i];
    g_feat_csr[pos] = make_float2(feat_vals[i], __int_as_float(feat_cols[i]));
}

// ---------------------------------------------------------------------------
// 4. FUSED: blocks [0, AB) scatter the adj COO into CSR; blocks [AB, ...)
//    run SpMM1 over the (already complete) feat CSR. The two halves touch
//    disjoint data, so no intra-kernel ordering is required — the grid
//    overlaps the latency-ish scatter with the gather-heavy SpMM1.
// ---------------------------------------------------------------------------
__global__ void adj_scatter_spmm1_kernel(const float* __restrict__ adj_vals,
                                         const int*   __restrict__ adj_rows,
                                         const int*   __restrict__ adj_cols,
                                         const float4* __restrict__ W4) {
    if (blockIdx.x < AB) {
        // ---- adj scatter ----
        int i = blockIdx.x * T + threadIdx.x;
        if (i >= ADJ_NNZ) return;
        int pos = __ldg(&g_adj_ptr[adj_rows[i]]) + g_adj_rank[i];
        g_adj_csr[pos] = make_float2(adj_vals[i], __int_as_float(adj_cols[i]));
        return;
    }

    // ---- SpMM1: XW[row,:] = sum_e val_e * W[col_e,:] ----
    int b    = blockIdx.x - AB;
    int row  = b * (T >> 5) + (threadIdx.x >> 5);
    if (row >= N_NODES) return;
    int lane = threadIdx.x & 31;

    int s = g_feat_ptr[row];
    int e = g_feat_ptr[row + 1];

    float4 acc = make_float4(0.f, 0.f, 0.f, 0.f);
    int j = s;
    for (; j + 2 <= e; j += 2) {
        float2 vc0 = __ldg(&g_feat_csr[j]);
        float2 vc1 = __ldg(&g_feat_csr[j + 1]);
        int c0 = __float_as_int(vc0.y);
        int c1 = __float_as_int(vc1.y);
        float4 w0 = __ldg(&W4[(size_t)c0 * 32 + lane]);
        float4 w1 = __ldg(&W4[(size_t)c1 * 32 + lane]);
        acc.x += vc0.x * w0.x + vc1.x * w1.x;
        acc.y += vc0.x * w0.y + vc1.x * w1.y;
        acc.z += vc0.x * w0.z + vc1.x * w1.z;
        acc.w += vc0.x * w0.w + vc1.x * w1.w;
    }
    for (; j < e; j++) {
        float2 vc = __ldg(&g_feat_csr[j]);
        int c = __float_as_int(vc.y);
        float4 w = __ldg(&W4[(size_t)c * 32 + lane]);
        acc.x += vc.x * w.x;
        acc.y += vc.x * w.y;
        acc.z += vc.x * w.z;
        acc.w += vc.x * w.w;
    }
    __half2 h0 = __floats2half2_rn(acc.x, acc.y);
    __half2 h1 = __floats2half2_rn(acc.z, acc.w);
    uint2 packed;
    packed.x = *reinterpret_cast<unsigned int*>(&h0);
    packed.y = *reinterpret_cast<unsigned int*>(&h1);
    g_xw2[(size_t)row * 32 + lane] = packed;
}

// ---------------------------------------------------------------------------
// 5. SpMM2 (CSR gather, fp16 XW) + fused bias + ReLU. Unrolled x4 (MLP=4).
// ---------------------------------------------------------------------------
__global__ void spmm2_csr_kernel(float4* __restrict__ out4,
                                 const float4* __restrict__ bias4) {
    int row  = blockIdx.x * (T >> 5) + (threadIdx.x >> 5);
    if (row >= N_NODES) return;
    int lane = threadIdx.x & 31;

    int s = g_adj_ptr[row];
    int e = g_adj_ptr[row + 1];

    float4 acc = make_float4(0.f, 0.f, 0.f, 0.f);
    int j = s;
    for (; j + 4 <= e; j += 4) {
        float2 vc0 = __ldg(&g_adj_csr[j]);
        float2 vc1 = __ldg(&g_adj_csr[j + 1]);
        float2 vc2 = __ldg(&g_adj_csr[j + 2]);
        float2 vc3 = __ldg(&g_adj_csr[j + 3]);
        uint2 r0 = __ldg(&g_xw2[(size_t)__float_as_int(vc0.y) * 32 + lane]);
        uint2 r1 = __ldg(&g_xw2[(size_t)__float_as_int(vc1.y) * 32 + lane]);
        uint2 r2 = __ldg(&g_xw2[(size_t)__float_as_int(vc2.y) * 32 + lane]);
        uint2 r3 = __ldg(&g_xw2[(size_t)__float_as_int(vc3.y) * 32 + lane]);
        float2 a0 = __half22float2(*reinterpret_cast<__half2*>(&r0.x));
        float2 b0 = __half22float2(*reinterpret_cast<__half2*>(&r0.y));
        float2 a1 = __half22float2(*reinterpret_cast<__half2*>(&r1.x));
        float2 b1 = __half22float2(*reinterpret_cast<__half2*>(&r1.y));
        float2 a2 = __half22float2(*reinterpret_cast<__half2*>(&r2.x));
        float2 b2 = __half22float2(*reinterpret_cast<__half2*>(&r2.y));
        float2 a3 = __half22float2(*reinterpret_cast<__half2*>(&r3.x));
        float2 b3 = __half22float2(*reinterpret_cast<__half2*>(&r3.y));
        acc.x += vc0.x * a0.x + vc1.x * a1.x + vc2.x * a2.x + vc3.x * a3.x;
        acc.y += vc0.x * a0.y + vc1.x * a1.y + vc2.x * a2.y + vc3.x * a3.y;
        acc.z += vc0.x * b0.x + vc1.x * b1.x + vc2.x * b2.x + vc3.x * b3.x;
        acc.w += vc0.x * b0.y + vc1.x * b1.y + vc2.x * b2.y + vc3.x * b3.y;
    }
    for (; j < e; j++) {
        float2 vc = __ldg(&g_adj_csr[j]);
        uint2 raw = __ldg(&g_xw2[(size_t)__float_as_int(vc.y) * 32 + lane]);
        float2 f0 = __half22float2(*reinterpret_cast<__half2*>(&raw.x));
        float2 f1 = __half22float2(*reinterpret_cast<__half2*>(&raw.y));
        acc.x += vc.x * f0.x;
        acc.y += vc.x * f0.y;
        acc.z += vc.x * f1.x;
        acc.w += vc.x * f1.y;
    }

    float4 b = __ldg(&bias4[lane]);
    acc.x = fmaxf(acc.x + b.x, 0.f);
    acc.y = fmaxf(acc.y + b.y, 0.f);
    acc.z = fmaxf(acc.z + b.z, 0.f);
    acc.w = fmaxf(acc.w + b.w, 0.f);
    out4[(size_t)row * 32 + lane] = acc;
}

// ---------------------------------------------------------------------------
extern "C" void kernel_launch(void* const* d_in, const int* in_sizes, int n_in,
                              void* d_out, int out_size) {
    const float* feat_vals = (const float*)d_in[0];
    const int*   feat_rows = (const int*)  d_in[1];
    const int*   feat_cols = (const int*)  d_in[2];
    const float* adj_vals  = (const float*)d_in[3];
    const int*   adj_rows  = (const int*)  d_in[4];
    const int*   adj_cols  = (const int*)  d_in[5];
    const float* weights   = (const float*)d_in[6];
    const float* bias_vec  = (const float*)d_in[7];
    float4* out4 = (float4*)d_out;

    hist_both_kernel<<<FB + AB, T>>>(feat_rows, adj_rows);

    scan_p1_kernel<<<2 * NBLK, TILE>>>();
    scan_p3_kernel<<<2 * NBLK, TILE>>>();

    scatter_feat_kernel<<<FB, T>>>(feat_vals, feat_rows, feat_cols);

    // adj scatter overlapped with SpMM1 (independent data, one grid)
    adj_scatter_spmm1_kernel<<<AB + ROWS_GRID, T>>>(adj_vals, adj_rows, adj_cols,
                                                    (const float4*)weights);

    spmm2_csr_kernel<<<ROWS_GRID, T>>>(out4, (const float4*)bias_vec);
}